// round 17
// baseline (speedup 1.0000x reference)
#include <cuda_runtime.h>
#include <cuda_bf16.h>
#include <math.h>

#define NN 50000
#define EE 400000
#define EP (EE + NN)   // edges + self loops = 450000

// ---------------- scratch (static __device__, no allocations) ----------------
__device__ __nv_bfloat162 g_h1b[(size_t)NN * 256]; // layer1 x@W1^T (bf16, 512/node)
__device__ float g_o1[(size_t)NN * 512];           // layer1 output (elu'd, fp32)
__device__ __nv_bfloat162 g_h2b[(size_t)NN * 64];  // layer2 (bf16, 128/node)
__device__ float g_o2[(size_t)NN * 128];
__device__ float g_h3[NN * 8];
__device__ float g_o3[NN * 8];
__device__ float g_s[NN * 4];
__device__ float g_d[NN * 4];
__device__ float g_s3[NN];
__device__ float g_d3[NN];
__device__ int   g_deg[NN];
__device__ int   g_rowptr[NN + 1];
__device__ int   g_cursor[NN];
__device__ int   g_adj[EP];                // src per in-edge (CSR by dst)
__device__ int   g_bsum[256];
__device__ int   g_boff[256];

__device__ __forceinline__ float lrelu(float x) { return x > 0.f ? x : 0.2f * x; }
__device__ __forceinline__ float eluf(float x)  { return x > 0.f ? x : expm1f(x); }
__device__ __forceinline__ float sel4(float a, float b, float c, float d, int h) {
    return h == 0 ? a : (h == 1 ? b : (h == 2 ? c : d));
}
__device__ __forceinline__ unsigned t32(float f) {
    unsigned u;
    asm("cvt.rna.tf32.f32 %0, %1;" : "=r"(u) : "f"(f));
    return u;
}
__device__ __forceinline__ void mma8(float* c, const unsigned* a, const unsigned* b) {
    asm volatile(
        "mma.sync.aligned.m16n8k8.row.col.f32.tf32.tf32.f32 "
        "{%0,%1,%2,%3}, {%4,%5,%6,%7}, {%8,%9}, {%0,%1,%2,%3};"
        : "+f"(c[0]), "+f"(c[1]), "+f"(c[2]), "+f"(c[3])
        : "r"(a[0]), "r"(a[1]), "r"(a[2]), "r"(a[3]), "r"(b[0]), "r"(b[1]));
}

// ---------------- CSR build ----------------
__global__ void k_initdeg() {
    int n = blockIdx.x * blockDim.x + threadIdx.x;
    if (n < NN) g_deg[n] = 1;   // self loop
}

__global__ void k_count(const int* __restrict__ ei) {
    int e = blockIdx.x * blockDim.x + threadIdx.x;
    if (e < EE) atomicAdd(&g_deg[ei[EE + e]], 1);
}

// block-local inclusive scan; writes local inclusive to rowptr[i+1], total to bsum
__global__ void k_scan1() {
    __shared__ int ws[8];
    int t = threadIdx.x;
    int lane = t & 31, w = t >> 5;
    int i = blockIdx.x * 256 + t;
    int v = (i < NN) ? g_deg[i] : 0;
    int s = v;
#pragma unroll
    for (int o = 1; o < 32; o <<= 1) {
        int u = __shfl_up_sync(0xffffffffu, s, o);
        if (lane >= o) s += u;
    }
    if (lane == 31) ws[w] = s;
    __syncthreads();
    if (w == 0 && lane < 8) {
        int x = ws[lane];
#pragma unroll
        for (int o = 1; o < 8; o <<= 1) {
            int u = __shfl_up_sync(0xffu, x, o);
            if (lane >= o) x += u;
        }
        ws[lane] = x;
    }
    __syncthreads();
    int incl = s + (w ? ws[w - 1] : 0);
    if (i < NN) g_rowptr[i + 1] = incl;
    if (t == 255) g_bsum[blockIdx.x] = incl;
}

// scan of 196 block sums -> exclusive offsets
__global__ void k_scan2() {
    __shared__ int ws[8];
    int t = threadIdx.x;
    int lane = t & 31, w = t >> 5;
    int v = (t < 196) ? g_bsum[t] : 0;
    int s = v;
#pragma unroll
    for (int o = 1; o < 32; o <<= 1) {
        int u = __shfl_up_sync(0xffffffffu, s, o);
        if (lane >= o) s += u;
    }
    if (lane == 31) ws[w] = s;
    __syncthreads();
    if (w == 0 && lane < 8) {
        int x = ws[lane];
#pragma unroll
        for (int o = 1; o < 8; o <<= 1) {
            int u = __shfl_up_sync(0xffu, x, o);
            if (lane >= o) x += u;
        }
        ws[lane] = x;
    }
    __syncthreads();
    int incl = s + (w ? ws[w - 1] : 0);
    if (t < 196) g_boff[t] = incl - v;   // exclusive
}

// add offsets + fused prep (self loop first, cursor init)
__global__ void k_scan3() {
    int i = blockIdx.x * 256 + threadIdx.x;
    if (i >= NN) return;
    int off = g_boff[blockIdx.x];
    int incl = g_rowptr[i + 1] + off;
    g_rowptr[i + 1] = incl;
    if (i == 0) g_rowptr[0] = 0;
    int r = incl - g_deg[i];
    g_adj[r] = i;            // self loop placed first
    g_cursor[i] = r + 1;
}

__global__ void k_scatter(const int* __restrict__ ei) {
    int e = blockIdx.x * blockDim.x + threadIdx.x;
    if (e < EE) {
        int src = ei[e], dst = ei[EE + e];
        int p = atomicAdd(&g_cursor[dst], 1);
        g_adj[p] = src;
    }
}

// ---------------- TF32 tensor-core GEMM: H[M,N] = A[M,K] * B[N,K]^T (bf16 out)
// Block tile 128x64, 8 warps (4m x 2n), warp tile 32x32, BK=32.
template<int LAYER>
__global__ void __launch_bounds__(256) gemm_tc(const float* __restrict__ Aext,
                                               const float* __restrict__ B,
                                               int M, int N, int K) {
    const float* A = (LAYER == 1) ? Aext : g_o1;
    __nv_bfloat162* H = (LAYER == 1) ? g_h1b : g_h2b;
    __shared__ unsigned As[128][36];
    __shared__ unsigned Bs[64][36];
    int tid = threadIdx.x;
    int lane = tid & 31, warp = tid >> 5;
    int wm = (warp & 3) * 32;
    int wn = (warp >> 2) * 32;
    int gid = lane >> 2, tig = lane & 3;
    int bm = blockIdx.y * 128, bn = blockIdx.x * 64;

    float acc[2][4][4];
#pragma unroll
    for (int mf = 0; mf < 2; mf++)
#pragma unroll
        for (int nf = 0; nf < 4; nf++)
#pragma unroll
            for (int k = 0; k < 4; k++) acc[mf][nf][k] = 0.f;

    int lr = tid >> 3;          // 0..31
    int lc = (tid & 7) * 4;     // 0,4,...,28
    int nk = K / 32;

    float4 pa[4], pb[2];
#pragma unroll
    for (int i = 0; i < 4; i++) {
        int row = bm + lr + 32 * i;
        pa[i] = (row < M) ? *(const float4*)(A + (size_t)row * K + lc)
                          : make_float4(0, 0, 0, 0);
    }
#pragma unroll
    for (int i = 0; i < 2; i++) {
        int row = bn + lr + 32 * i;
        pb[i] = *(const float4*)(B + (size_t)row * K + lc);
    }
#pragma unroll
    for (int i = 0; i < 4; i++) {
        As[lr + 32 * i][lc + 0] = t32(pa[i].x);
        As[lr + 32 * i][lc + 1] = t32(pa[i].y);
        As[lr + 32 * i][lc + 2] = t32(pa[i].z);
        As[lr + 32 * i][lc + 3] = t32(pa[i].w);
    }
#pragma unroll
    for (int i = 0; i < 2; i++) {
        Bs[lr + 32 * i][lc + 0] = t32(pb[i].x);
        Bs[lr + 32 * i][lc + 1] = t32(pb[i].y);
        Bs[lr + 32 * i][lc + 2] = t32(pb[i].z);
        Bs[lr + 32 * i][lc + 3] = t32(pb[i].w);
    }
    __syncthreads();

    for (int it = 0; it < nk; it++) {
        if (it + 1 < nk) {
            int koff = (it + 1) * 32;
#pragma unroll
            for (int i = 0; i < 4; i++) {
                int row = bm + lr + 32 * i;
                pa[i] = (row < M) ? *(const float4*)(A + (size_t)row * K + koff + lc)
                                  : make_float4(0, 0, 0, 0);
            }
#pragma unroll
            for (int i = 0; i < 2; i++) {
                int row = bn + lr + 32 * i;
                pb[i] = *(const float4*)(B + (size_t)row * K + koff + lc);
            }
        }
#pragma unroll
        for (int ks = 0; ks < 4; ks++) {
            int kk = ks * 8;
            unsigned a[2][4], b[4][2];
#pragma unroll
            for (int mf = 0; mf < 2; mf++) {
                int r = wm + mf * 16 + gid;
                a[mf][0] = As[r][kk + tig];
                a[mf][1] = As[r + 8][kk + tig];
                a[mf][2] = As[r][kk + tig + 4];
                a[mf][3] = As[r + 8][kk + tig + 4];
            }
#pragma unroll
            for (int nf = 0; nf < 4; nf++) {
                int r = wn + nf * 8 + gid;
                b[nf][0] = Bs[r][kk + tig];
                b[nf][1] = Bs[r][kk + tig + 4];
            }
#pragma unroll
            for (int mf = 0; mf < 2; mf++)
#pragma unroll
                for (int nf = 0; nf < 4; nf++) mma8(acc[mf][nf], a[mf], b[nf]);
        }
        __syncthreads();
        if (it + 1 < nk) {
#pragma unroll
            for (int i = 0; i < 4; i++) {
                As[lr + 32 * i][lc + 0] = t32(pa[i].x);
                As[lr + 32 * i][lc + 1] = t32(pa[i].y);
                As[lr + 32 * i][lc + 2] = t32(pa[i].z);
                As[lr + 32 * i][lc + 3] = t32(pa[i].w);
            }
#pragma unroll
            for (int i = 0; i < 2; i++) {
                Bs[lr + 32 * i][lc + 0] = t32(pb[i].x);
                Bs[lr + 32 * i][lc + 1] = t32(pb[i].y);
                Bs[lr + 32 * i][lc + 2] = t32(pb[i].z);
                Bs[lr + 32 * i][lc + 3] = t32(pb[i].w);
            }
            __syncthreads();
        }
    }

    int nh = N >> 1;
#pragma unroll
    for (int mf = 0; mf < 2; mf++)
#pragma unroll
        for (int nf = 0; nf < 4; nf++) {
            int r0 = bm + wm + mf * 16 + gid;
            int c0 = bn + wn + nf * 8 + 2 * tig;
            if (r0 < M)
                H[(size_t)r0 * nh + (c0 >> 1)] =
                    __float22bfloat162_rn(make_float2(acc[mf][nf][0], acc[mf][nf][1]));
            if (r0 + 8 < M)
                H[(size_t)(r0 + 8) * nh + (c0 >> 1)] =
                    __float22bfloat162_rn(make_float2(acc[mf][nf][2], acc[mf][nf][3]));
        }
}

// ---------------- attention coefficients: s[n,h]=h·a_s, d[n,h]=h·a_d --------
template<int CT>
__global__ void k_sd(const float* __restrict__ as, const float* __restrict__ ad) {
    int w = (blockIdx.x * blockDim.x + threadIdx.x) >> 5;
    int lane = threadIdx.x & 31;
    if (w >= NN) return;
    float ps[4] = {0, 0, 0, 0}, pd[4] = {0, 0, 0, 0};
    if (CT == 512) {
        const float4* hp = (const float4*)g_h1b + (size_t)w * 64;
#pragma unroll
        for (int i = 0; i < 2; i++) {
            float4 hv = hp[lane + 32 * i];
            const __nv_bfloat162* hb = (const __nv_bfloat162*)&hv;
            int base = 256 * i + 8 * lane;
            float s8 = 0.f, d8 = 0.f;
#pragma unroll
            for (int k = 0; k < 4; k++) {
                float2 f = __bfloat1622float2(hb[k]);
                s8 += f.x * as[base + 2 * k] + f.y * as[base + 2 * k + 1];
                d8 += f.x * ad[base + 2 * k] + f.y * ad[base + 2 * k + 1];
            }
            int hd = 2 * i + (lane >> 4);
#pragma unroll
            for (int k = 0; k < 4; k++) {
                ps[k] += (hd == k) ? s8 : 0.f;
                pd[k] += (hd == k) ? d8 : 0.f;
            }
        }
    } else {
        uint2 hv = ((const uint2*)(g_h2b + (size_t)w * 64))[lane];
        float2 f0 = __bfloat1622float2(*(__nv_bfloat162*)&hv.x);
        float2 f1 = __bfloat1622float2(*(__nv_bfloat162*)&hv.y);
        int base = 4 * lane;
        float s4 = f0.x * as[base] + f0.y * as[base + 1] + f1.x * as[base + 2] + f1.y * as[base + 3];
        float d4 = f0.x * ad[base] + f0.y * ad[base + 1] + f1.x * ad[base + 2] + f1.y * ad[base + 3];
        int hd = lane >> 3;
#pragma unroll
        for (int k = 0; k < 4; k++) {
            ps[k] += (hd == k) ? s4 : 0.f;
            pd[k] += (hd == k) ? d4 : 0.f;
        }
    }
#pragma unroll
    for (int o = 16; o; o >>= 1) {
#pragma unroll
        for (int k = 0; k < 4; k++) {
            ps[k] += __shfl_xor_sync(0xffffffffu, ps[k], o);
            pd[k] += __shfl_xor_sync(0xffffffffu, pd[k], o);
        }
    }
    if (lane == 0) {
#pragma unroll
        for (int k = 0; k < 4; k++) { g_s[4 * w + k] = ps[k]; g_d[4 * w + k] = pd[k]; }
    }
}

// ---------------- single-pass segment softmax + aggregation ----------------
// No max-subtraction (|e| small, shift-invariant ratio); den is lane-redundant.
// 4-edge software pipeline to expose memory-level parallelism.
template<int CT>
__global__ void k_agg(const float* __restrict__ bias) {
    float* __restrict__ out = (CT == 512) ? g_o1 : g_o2;
    int w = (blockIdx.x * blockDim.x + threadIdx.x) >> 5;
    int lane = threadIdx.x & 31;
    if (w >= NN) return;
    int beg = g_rowptr[w], end = g_rowptr[w + 1];
    float4 dv = *(const float4*)(g_d + 4 * w);
    float d0 = 0.f, d1 = 0.f, d2 = 0.f, d3 = 0.f;

    if (CT == 512) {
        float acc[2][8];
#pragma unroll
        for (int i = 0; i < 2; i++)
#pragma unroll
            for (int k = 0; k < 8; k++) acc[i][k] = 0.f;
        int hd0 = lane >> 4;
        int j = beg;
        int nb = beg + ((end - beg) & ~3);
        for (; j < nb; j += 4) {
            int srcs[4];
#pragma unroll
            for (int t = 0; t < 4; t++) srcs[t] = g_adj[j + t];
            float4 svv[4];
#pragma unroll
            for (int t = 0; t < 4; t++) svv[t] = *(const float4*)(g_s + 4 * srcs[t]);
            float4 v0[4], v1[4];
#pragma unroll
            for (int t = 0; t < 4; t++) {
                const float4* hp = (const float4*)g_h1b + (size_t)srcs[t] * 64;
                v0[t] = hp[lane];
                v1[t] = hp[lane + 32];
            }
#pragma unroll
            for (int t = 0; t < 4; t++) {
                float x0 = __expf(lrelu(svv[t].x + dv.x));
                float x1 = __expf(lrelu(svv[t].y + dv.y));
                float x2 = __expf(lrelu(svv[t].z + dv.z));
                float x3 = __expf(lrelu(svv[t].w + dv.w));
                d0 += x0; d1 += x1; d2 += x2; d3 += x3;
                float w0 = sel4(x0, x1, x2, x3, hd0);
                float w1 = sel4(x0, x1, x2, x3, 2 + hd0);
                const __nv_bfloat162* b0 = (const __nv_bfloat162*)&v0[t];
                const __nv_bfloat162* b1 = (const __nv_bfloat162*)&v1[t];
#pragma unroll
                for (int k = 0; k < 4; k++) {
                    float2 f0 = __bfloat1622float2(b0[k]);
                    float2 f1 = __bfloat1622float2(b1[k]);
                    acc[0][2 * k]     += w0 * f0.x;
                    acc[0][2 * k + 1] += w0 * f0.y;
                    acc[1][2 * k]     += w1 * f1.x;
                    acc[1][2 * k + 1] += w1 * f1.y;
                }
            }
        }
        for (; j < end; j++) {
            int src = g_adj[j];
            float4 sv = *(const float4*)(g_s + 4 * src);
            const float4* hp = (const float4*)g_h1b + (size_t)src * 64;
            float4 v0 = hp[lane];
            float4 v1 = hp[lane + 32];
            float x0 = __expf(lrelu(sv.x + dv.x));
            float x1 = __expf(lrelu(sv.y + dv.y));
            float x2 = __expf(lrelu(sv.z + dv.z));
            float x3 = __expf(lrelu(sv.w + dv.w));
            d0 += x0; d1 += x1; d2 += x2; d3 += x3;
            float w0 = sel4(x0, x1, x2, x3, hd0);
            float w1 = sel4(x0, x1, x2, x3, 2 + hd0);
            const __nv_bfloat162* b0 = (const __nv_bfloat162*)&v0;
            const __nv_bfloat162* b1 = (const __nv_bfloat162*)&v1;
#pragma unroll
            for (int k = 0; k < 4; k++) {
                float2 f0 = __bfloat1622float2(b0[k]);
                float2 f1 = __bfloat1622float2(b1[k]);
                acc[0][2 * k]     += w0 * f0.x;
                acc[0][2 * k + 1] += w0 * f0.y;
                acc[1][2 * k]     += w1 * f1.x;
                acc[1][2 * k + 1] += w1 * f1.y;
            }
        }
        float inv0 = 1.f / sel4(d0, d1, d2, d3, hd0);
        float inv1 = 1.f / sel4(d0, d1, d2, d3, 2 + hd0);
        float* op = out + (size_t)w * 512;
#pragma unroll
        for (int i = 0; i < 2; i++) {
            int base = 256 * i + 8 * lane;
            float inv = i ? inv1 : inv0;
            float4 bv0 = *(const float4*)(bias + base);
            float4 bv1 = *(const float4*)(bias + base + 4);
            float4 r0, r1;
            r0.x = eluf(acc[i][0] * inv + bv0.x);
            r0.y = eluf(acc[i][1] * inv + bv0.y);
            r0.z = eluf(acc[i][2] * inv + bv0.z);
            r0.w = eluf(acc[i][3] * inv + bv0.w);
            r1.x = eluf(acc[i][4] * inv + bv1.x);
            r1.y = eluf(acc[i][5] * inv + bv1.y);
            r1.z = eluf(acc[i][6] * inv + bv1.z);
            r1.w = eluf(acc[i][7] * inv + bv1.w);
            *(float4*)(op + base) = r0;
            *(float4*)(op + base + 4) = r1;
        }
    } else {
        float acc[4] = {0, 0, 0, 0};
        int hd = lane >> 3;
        int j = beg;
        int nb = beg + ((end - beg) & ~3);
        for (; j < nb; j += 4) {
            int srcs[4];
#pragma unroll
            for (int t = 0; t < 4; t++) srcs[t] = g_adj[j + t];
            float4 svv[4];
#pragma unroll
            for (int t = 0; t < 4; t++) svv[t] = *(const float4*)(g_s + 4 * srcs[t]);
            uint2 hv[4];
#pragma unroll
            for (int t = 0; t < 4; t++)
                hv[t] = ((const uint2*)(g_h2b + (size_t)srcs[t] * 64))[lane];
#pragma unroll
            for (int t = 0; t < 4; t++) {
                float x0 = __expf(lrelu(svv[t].x + dv.x));
                float x1 = __expf(lrelu(svv[t].y + dv.y));
                float x2 = __expf(lrelu(svv[t].z + dv.z));
                float x3 = __expf(lrelu(svv[t].w + dv.w));
                d0 += x0; d1 += x1; d2 += x2; d3 += x3;
                float wg = sel4(x0, x1, x2, x3, hd);
                float2 f0 = __bfloat1622float2(*(__nv_bfloat162*)&hv[t].x);
                float2 f1 = __bfloat1622float2(*(__nv_bfloat162*)&hv[t].y);
                acc[0] += wg * f0.x; acc[1] += wg * f0.y;
                acc[2] += wg * f1.x; acc[3] += wg * f1.y;
            }
        }
        for (; j < end; j++) {
            int src = g_adj[j];
            float4 sv = *(const float4*)(g_s + 4 * src);
            uint2 hv = ((const uint2*)(g_h2b + (size_t)src * 64))[lane];
            float x0 = __expf(lrelu(sv.x + dv.x));
            float x1 = __expf(lrelu(sv.y + dv.y));
            float x2 = __expf(lrelu(sv.z + dv.z));
            float x3 = __expf(lrelu(sv.w + dv.w));
            d0 += x0; d1 += x1; d2 += x2; d3 += x3;
            float wg = sel4(x0, x1, x2, x3, hd);
            float2 f0 = __bfloat1622float2(*(__nv_bfloat162*)&hv.x);
            float2 f1 = __bfloat1622float2(*(__nv_bfloat162*)&hv.y);
            acc[0] += wg * f0.x; acc[1] += wg * f0.y;
            acc[2] += wg * f1.x; acc[3] += wg * f1.y;
        }
        float inv = 1.f / sel4(d0, d1, d2, d3, hd);
        int base = 4 * lane;
        float4 bv = *(const float4*)(bias + base);
        float4 r;
        r.x = eluf(acc[0] * inv + bv.x);
        r.y = eluf(acc[1] * inv + bv.y);
        r.z = eluf(acc[2] * inv + bv.z);
        r.w = eluf(acc[3] * inv + bv.w);
        *(float4*)(out + (size_t)w * 128 + base) = r;
    }
}

// ---------------- layer3: h3 = o2 @ W3^T (8 outs) + s3/d3, warp per node ----
__global__ void k_l3(const float* __restrict__ W3, const float* __restrict__ a3s,
                     const float* __restrict__ a3d) {
    int w = (blockIdx.x * blockDim.x + threadIdx.x) >> 5;
    int lane = threadIdx.x & 31;
    if (w >= NN) return;
    float4 xv = ((const float4*)(g_o2 + (size_t)w * 128))[lane];
    float p[8];
#pragma unroll
    for (int o = 0; o < 8; o++) {
        float4 wv = ((const float4*)(W3 + o * 128))[lane];
        p[o] = xv.x * wv.x + xv.y * wv.y + xv.z * wv.z + xv.w * wv.w;
    }
#pragma unroll
    for (int off = 16; off; off >>= 1)
#pragma unroll
        for (int o = 0; o < 8; o++) p[o] += __shfl_xor_sync(0xffffffffu, p[o], off);
    if (lane == 0) {
        float ss = 0.f, dd = 0.f;
#pragma unroll
        for (int o = 0; o < 8; o++) {
            g_h3[w * 8 + o] = p[o];
            ss += p[o] * a3s[o];
            dd += p[o] * a3d[o];
        }
        g_s3[w] = ss; g_d3[w] = dd;
    }
}

// ---------------- layer3 aggregation: thread per node, single pass ----------
__global__ void k_agg3(const float* __restrict__ b3) {
    int n = blockIdx.x * blockDim.x + threadIdx.x;
    if (n >= NN) return;
    int beg = g_rowptr[n], end = g_rowptr[n + 1];
    float dv = g_d3[n];
    float den = 0.f;
    float4 a0 = make_float4(0, 0, 0, 0), a1 = make_float4(0, 0, 0, 0);
    int j = beg;
    int nb = beg + ((end - beg) & ~3);
    for (; j < nb; j += 4) {
        int srcs[4];
#pragma unroll
        for (int t = 0; t < 4; t++) srcs[t] = g_adj[j + t];
        float sv[4];
#pragma unroll
        for (int t = 0; t < 4; t++) sv[t] = g_s3[srcs[t]];
        float4 h0[4], h1[4];
#pragma unroll
        for (int t = 0; t < 4; t++) {
            h0[t] = *(const float4*)(g_h3 + (size_t)srcs[t] * 8);
            h1[t] = *(const float4*)(g_h3 + (size_t)srcs[t] * 8 + 4);
        }
#pragma unroll
        for (int t = 0; t < 4; t++) {
            float ex = __expf(lrelu(sv[t] + dv));
            den += ex;
            a0.x += ex * h0[t].x; a0.y += ex * h0[t].y;
            a0.z += ex * h0[t].z; a0.w += ex * h0[t].w;
            a1.x += ex * h1[t].x; a1.y += ex * h1[t].y;
            a1.z += ex * h1[t].z; a1.w += ex * h1[t].w;
        }
    }
    for (; j < end; j++) {
        int src = g_adj[j];
        float ex = __expf(lrelu(g_s3[src] + dv));
        den += ex;
        float4 h0 = *(const float4*)(g_h3 + (size_t)src * 8);
        float4 h1 = *(const float4*)(g_h3 + (size_t)src * 8 + 4);
        a0.x += ex * h0.x; a0.y += ex * h0.y; a0.z += ex * h0.z; a0.w += ex * h0.w;
        a1.x += ex * h1.x; a1.y += ex * h1.y; a1.z += ex * h1.z; a1.w += ex * h1.w;
    }
    float inv = 1.f / den;
    float4 r0, r1;
    r0.x = eluf(a0.x * inv + b3[0]); r0.y = eluf(a0.y * inv + b3[1]);
    r0.z = eluf(a0.z * inv + b3[2]); r0.w = eluf(a0.w * inv + b3[3]);
    r1.x = eluf(a1.x * inv + b3[4]); r1.y = eluf(a1.y * inv + b3[5]);
    r1.z = eluf(a1.z * inv + b3[6]); r1.w = eluf(a1.w * inv + b3[7]);
    *(float4*)(g_o3 + (size_t)n * 8) = r0;
    *(float4*)(g_o3 + (size_t)n * 8 + 4) = r1;
}

// ---------------- edge MLP ----------------
__global__ void k_mlp(const int* __restrict__ ei, const float* __restrict__ ea,
                      const float* __restrict__ yr, const float* __restrict__ qt,
                      const float* __restrict__ f1w, const float* __restrict__ f1b,
                      const float* __restrict__ f2w, const float* __restrict__ f2b,
                      float* __restrict__ out) {
    __shared__ float w1s[16 * 19], b1s[16], w2s[16];
    __shared__ float b2s;
    int t = threadIdx.x;
    for (int i = t; i < 16 * 19; i += blockDim.x) w1s[i] = f1w[i];
    if (t < 16) { b1s[t] = f1b[t]; w2s[t] = f2w[t]; }
    if (t == 0) b2s = f2b[0];
    __syncthreads();
    int e = blockIdx.x * blockDim.x + t;
    if (e >= EE) return;
    int src = ei[e], dst = ei[EE + e];
    float4 s0 = *(const float4*)(g_o3 + (size_t)src * 8);
    float4 s1 = *(const float4*)(g_o3 + (size_t)src * 8 + 4);
    float4 q0 = *(const float4*)(g_o3 + (size_t)dst * 8);
    float4 q1 = *(const float4*)(g_o3 + (size_t)dst * 8 + 4);
    float z16 = ea[e], z17 = yr[e], z18 = qt[e];
    float res = b2s;
#pragma unroll
    for (int o = 0; o < 16; o++) {
        const float* wr = &w1s[o * 19];
        float a = b1s[o]
            + wr[0] * s0.x + wr[1] * s0.y + wr[2] * s0.z + wr[3] * s0.w
            + wr[4] * s1.x + wr[5] * s1.y + wr[6] * s1.z + wr[7] * s1.w
            + wr[8] * q0.x + wr[9] * q0.y + wr[10] * q0.z + wr[11] * q0.w
            + wr[12] * q1.x + wr[13] * q1.y + wr[14] * q1.z + wr[15] * q1.w
            + wr[16] * z16 + wr[17] * z17 + wr[18] * z18;
        res += w2s[o] * fmaxf(a, 0.f);
    }
    out[e] = res;
}

// ---------------- host ----------------
extern "C" void kernel_launch(void* const* d_in, const int* in_sizes, int n_in,
                              void* d_out, int out_size) {
    const float* x   = (const float*)d_in[0];
    const int*   ei  = (const int*)d_in[1];
    const float* ea  = (const float*)d_in[2];
    const float* yr  = (const float*)d_in[3];
    const float* qt  = (const float*)d_in[4];
    const float* W1  = (const float*)d_in[5];
    const float* a1s = (const float*)d_in[6];
    const float* a1d = (const float*)d_in[7];
    const float* b1  = (const float*)d_in[8];
    const float* W2  = (const float*)d_in[9];
    const float* a2s = (const float*)d_in[10];
    const float* a2d = (const float*)d_in[11];
    const float* b2  = (const float*)d_in[12];
    const float* W3  = (const float*)d_in[13];
    const float* a3s = (const float*)d_in[14];
    const float* a3d = (const float*)d_in[15];
    const float* b3  = (const float*)d_in[16];
    const float* f1w = (const float*)d_in[17];
    const float* f1b = (const float*)d_in[18];
    const float* f2w = (const float*)d_in[19];
    const float* f2b = (const float*)d_in[20];
    float* out = (float*)d_out;

    // CSR build (dst-sorted adjacency, self loop first per node)
    int nb = (NN + 255) / 256;   // 196
    k_initdeg<<<nb, 256>>>();
    k_count<<<(EE + 255) / 256, 256>>>(ei);
    k_scan1<<<nb, 256>>>();
    k_scan2<<<1, 256>>>();
    k_scan3<<<nb, 256>>>();
    k_scatter<<<(EE + 255) / 256, 256>>>(ei);

    int wblocks = (NN * 32 + 255) / 256;   // warp-per-node launches

    // layer 1: 128 -> 4x128 (tf32 tensor cores, bf16 out)
    dim3 g1(512 / 64, (NN + 127) / 128);
    gemm_tc<1><<<g1, 256>>>(x, W1, NN, 512, 128);
    k_sd<512><<<wblocks, 256>>>(a1s, a1d);
    k_agg<512><<<wblocks, 256>>>(b1);

    // layer 2: 512 -> 4x32 (tf32 tensor cores, bf16 out)
    dim3 g2(128 / 64, (NN + 127) / 128);
    gemm_tc<2><<<g2, 256>>>(nullptr, W2, NN, 128, 512);
    k_sd<128><<<wblocks, 256>>>(a2s, a2d);
    k_agg<128><<<wblocks, 256>>>(b2);

    // layer 3: 128 -> 1x8 (gemm + s/d fused), then aggregation
    k_l3<<<wblocks, 256>>>(W3, a3s, a3d);
    k_agg3<<<nb, 256>>>(b3);

    // edge MLP
    k_mlp<<<(EE + 255) / 256, 256>>>(ei, ea, yr, qt, f1w, f1b, f2w, f2b, out);
}